// round 11
// baseline (speedup 1.0000x reference)
#include <cuda_runtime.h>
#include <cuda_bf16.h>

// ts_std: sliding-window population std over time, per feature.
// x: [B=64, T=2048, F=256] fp32 -> out: [B, S=2017, F] fp32, window=32, stride=1.
//
// Thread = one (b, f-pair) column, float2-vectorized over features (halves
// LSU instruction count vs scalar; warp accesses stay 256B coalesced).
// Register ring buffer of W=32 float2 values, incremental window-sum updates,
// exact re-summation at every 32-step chunk boundary to bound fp32 drift
// (<= 32 incremental steps of error, ~1e-5 rel on std).
// T split into NSEG segments (31-element halo each) for occupancy.
// Fast path batches loads in groups of 8 for explicit MLP.
// Streaming cache hints: output never re-read (__stcs), input read ~once (__ldcs).
// All addressing in 32-bit (max offset 16.7M float2 < 2^31) to cut IMAD.WIDE chains.

#define BB 64
#define TT 2048
#define FF 256
#define WW 32
#define SS (TT - WW + 1)            // 2017
#define SEG 256
#define NSEG ((SS + SEG - 1) / SEG) // 8
#define LB 8                        // load batch (MLP group)
#define FV (FF / 2)                 // float2 lanes per time row = 128

__global__ void ts_std_kernel(const float* __restrict__ x,
                              float* __restrict__ out) {
    const int fv  = threadIdx.x;    // float2 feature index (0..127)
    const int b   = blockIdx.x;     // batch
    const int seg = blockIdx.y;     // time segment

    const int s_begin = seg * SEG;
    const int s_end   = min(SS, s_begin + SEG);

    const float2* __restrict__ xp =
        (const float2*)(x + b * (TT * FF)) + fv;    // base + feature lane
    float2* __restrict__ op =
        (float2*)(out + b * (SS * FF)) + fv;

    // Prime the ring with x[b, s_begin .. s_begin+31, fpair] (independent loads).
    float2 buf[WW];
    {
        const float2* __restrict__ p0 = xp + s_begin * FV;
        #pragma unroll
        for (int j = 0; j < WW; j++) {
            buf[j] = __ldcs(p0 + j * FV);
        }
    }

    const float inv_w = 1.0f / (float)WW;

    int s = s_begin;
    while (s < s_end) {
        // Exact re-sum at chunk boundary: kills incremental drift.
        float s1x = 0.0f, s1y = 0.0f, s2x = 0.0f, s2y = 0.0f;
        #pragma unroll
        for (int j = 0; j < WW; j++) {
            s1x += buf[j].x;  s1y += buf[j].y;
            s2x = fmaf(buf[j].x, buf[j].x, s2x);
            s2y = fmaf(buf[j].y, buf[j].y, s2y);
        }

        if ((s + WW <= s_end) && (s + 2 * WW <= TT)) {
            // Fast path: 32 outputs / 32 unguarded loads, in 4 batches of 8.
            // Loads issued up-front per batch -> MLP = 8 (x2 words each).
            const float2* __restrict__ ld = xp + (s + WW) * FV;
            float2* __restrict__       st = op + s * FV;
            #pragma unroll
            for (int g = 0; g < WW / LB; g++) {
                float2 nxt[LB];
                #pragma unroll
                for (int k = 0; k < LB; k++) {
                    nxt[k] = __ldcs(ld + (g * LB + k) * FV);
                }
                #pragma unroll
                for (int k = 0; k < LB; k++) {
                    const int j = g * LB + k;
                    float mx = s1x * inv_w, my = s1y * inv_w;
                    float vx = fmaf(-mx, mx, s2x * inv_w);
                    float vy = fmaf(-my, my, s2y * inv_w);
                    float2 o;
                    o.x = __fsqrt_rn(fmaxf(vx, 0.0f));
                    o.y = __fsqrt_rn(fmaxf(vy, 0.0f));
                    __stcs(st + j * FV, o);

                    float2 xo = buf[j];
                    float2 xn = nxt[k];
                    s1x += xn.x - xo.x;  s1y += xn.y - xo.y;
                    s2x += fmaf(xn.x, xn.x, -xo.x * xo.x);
                    s2y += fmaf(xn.y, xn.y, -xo.y * xo.y);
                    buf[j] = xn;
                }
            }
            s += WW;
        } else {
            // Tail: predicated, fully unrolled (static ring indices only).
            const int nj = s_end - s;
            #pragma unroll
            for (int j = 0; j < WW; j++) {
                if (j < nj) {
                    float mx = s1x * inv_w, my = s1y * inv_w;
                    float vx = fmaf(-mx, mx, s2x * inv_w);
                    float vy = fmaf(-my, my, s2y * inv_w);
                    float2 o;
                    o.x = __fsqrt_rn(fmaxf(vx, 0.0f));
                    o.y = __fsqrt_rn(fmaxf(vy, 0.0f));
                    __stcs(op + (s + j) * FV, o);

                    const int tl = s + WW + j;
                    if (tl < TT) {
                        float2 xo = buf[j];
                        float2 xn = __ldcs(xp + tl * FV);
                        s1x += xn.x - xo.x;  s1y += xn.y - xo.y;
                        s2x += fmaf(xn.x, xn.x, -xo.x * xo.x);
                        s2y += fmaf(xn.y, xn.y, -xo.y * xo.y);
                        buf[j] = xn;
                    }
                }
            }
            s = s_end;
        }
    }
}

extern "C" void kernel_launch(void* const* d_in, const int* in_sizes, int n_in,
                              void* d_out, int out_size) {
    const float* x = (const float*)d_in[0];
    float* out = (float*)d_out;
    (void)in_sizes; (void)n_in; (void)out_size;

    dim3 grid(BB, NSEG);
    dim3 block(FV);
    ts_std_kernel<<<grid, block>>>(x, out);
}

// round 13
// speedup vs baseline: 1.1149x; 1.1149x over previous
#include <cuda_runtime.h>
#include <cuda_bf16.h>

// ts_std: sliding-window population std over time, per feature.
// x: [B=64, T=2048, F=256] fp32 -> out: [B, S=2017, F] fp32, window=32, stride=1.
//
// R11 redesign after first profile (59.9us, occ=20.7%, dram=52%): the kernel
// was GRID-limited (512 CTAs = 3.46 CTAs/SM). Changes:
//  - SEG 256 -> 128 (1024 CTAs, ~7/SM for one full wave).
//  - Drop the 64-reg ring buffer; run a second "old" load stream re-reading
//    x[s] (loaded 32 rows earlier -> L1/L2 hit, no extra DRAM traffic).
//    Registers ~116 -> ~60, __launch_bounds__(128,7) -> ~28 warps/SM.
//  - New stream: default caching loads (so old stream hits cache);
//    old stream: __ldcs (last touch); stores: __stcs.
//  - Incremental sums only (<=128 steps/segment): drift ~1e-5 rel, gate 1e-3.

#define BB 64
#define TT 2048
#define FF 256
#define WW 32
#define SS (TT - WW + 1)            // 2017
#define SEG 128
#define NSEG ((SS + SEG - 1) / SEG) // 16
#define LB 4                        // outputs per fast-path chunk
#define FV (FF / 2)                 // float2 lanes per time row = 128

__global__ __launch_bounds__(128, 7)
void ts_std_kernel(const float* __restrict__ x, float* __restrict__ out) {
    const int fv  = threadIdx.x;    // float2 feature index (0..127)
    const int b   = blockIdx.x;     // batch
    const int seg = blockIdx.y;     // time segment

    const int s_begin = seg * SEG;
    const int s_end   = min(SS, s_begin + SEG);

    const float2* __restrict__ xp =
        (const float2*)(x + b * (TT * FF)) + fv;
    float2* __restrict__ op =
        (float2*)(out + b * (SS * FF)) + fv;

    const float inv_w = 1.0f / (float)WW;

    // Prime: accumulate rows [s_begin, s_begin+32) in batches of 8 (MLP).
    float s1x = 0.0f, s1y = 0.0f, s2x = 0.0f, s2y = 0.0f;
    {
        const float2* __restrict__ p0 = xp + s_begin * FV;
        #pragma unroll
        for (int jb = 0; jb < WW; jb += 8) {
            float2 t[8];
            #pragma unroll
            for (int k = 0; k < 8; k++) {
                t[k] = p0[(jb + k) * FV];   // caching load: re-read later as "old"
            }
            #pragma unroll
            for (int k = 0; k < 8; k++) {
                s1x += t[k].x;  s1y += t[k].y;
                s2x = fmaf(t[k].x, t[k].x, s2x);
                s2y = fmaf(t[k].y, t[k].y, s2y);
            }
        }
    }

    int s = s_begin;

    // Fast path: LB outputs per chunk; both streams unguarded.
    // Bounds: new rows s+WW .. s+WW+LB-1 need s+WW+LB <= TT;
    //         chunk outputs need s+LB <= s_end.
    for (; (s + LB <= s_end) && (s + WW + LB <= TT); s += LB) {
        float2 nxt[LB], old[LB];
        const float2* __restrict__ ldn = xp + (s + WW) * FV;
        const float2* __restrict__ ldo = xp + s * FV;
        #pragma unroll
        for (int k = 0; k < LB; k++) {
            nxt[k] = ldn[k * FV];           // caching load (old stream reuses)
        }
        #pragma unroll
        for (int k = 0; k < LB; k++) {
            old[k] = __ldcs(ldo + k * FV);  // last touch of this row
        }
        float2* __restrict__ st = op + s * FV;
        #pragma unroll
        for (int k = 0; k < LB; k++) {
            float mx = s1x * inv_w, my = s1y * inv_w;
            float vx = fmaf(-mx, mx, s2x * inv_w);
            float vy = fmaf(-my, my, s2y * inv_w);
            float2 o;
            o.x = __fsqrt_rn(fmaxf(vx, 0.0f));
            o.y = __fsqrt_rn(fmaxf(vy, 0.0f));
            __stcs(st + k * FV, o);

            // advance window [s+k, s+k+W) -> [s+k+1, ...)
            s1x += nxt[k].x - old[k].x;
            s1y += nxt[k].y - old[k].y;
            s2x += fmaf(nxt[k].x, nxt[k].x, -old[k].x * old[k].x);
            s2y += fmaf(nxt[k].y, nxt[k].y, -old[k].y * old[k].y);
        }
    }

    // Tail: one output at a time, guarded update.
    for (; s < s_end; s++) {
        float mx = s1x * inv_w, my = s1y * inv_w;
        float vx = fmaf(-mx, mx, s2x * inv_w);
        float vy = fmaf(-my, my, s2y * inv_w);
        float2 o;
        o.x = __fsqrt_rn(fmaxf(vx, 0.0f));
        o.y = __fsqrt_rn(fmaxf(vy, 0.0f));
        __stcs(op + s * FV, o);

        if (s + WW < TT) {
            float2 xn = xp[(s + WW) * FV];
            float2 xo = __ldcs(xp + s * FV);
            s1x += xn.x - xo.x;  s1y += xn.y - xo.y;
            s2x += fmaf(xn.x, xn.x, -xo.x * xo.x);
            s2y += fmaf(xn.y, xn.y, -xo.y * xo.y);
        }
    }
}

extern "C" void kernel_launch(void* const* d_in, const int* in_sizes, int n_in,
                              void* d_out, int out_size) {
    const float* x = (const float*)d_in[0];
    float* out = (float*)d_out;
    (void)in_sizes; (void)n_in; (void)out_size;

    dim3 grid(BB, NSEG);
    dim3 block(FV);
    ts_std_kernel<<<grid, block>>>(x, out);
}